// round 13
// baseline (speedup 1.0000x reference)
#include <cuda_runtime.h>
#include <cuda_fp16.h>

#define D 64
#define MAXN 100000
#define MAXE 1200000
#define GMAX 64
#define EPS 1e-5f
#define TPB 256
#define NTILES 512

__device__ __half2 g_Xh[(size_t)MAXN * 32];   // agg input  (gemm output / staged x)
__device__ __half2 g_Ah[(size_t)MAXN * 32];   // agg output (gemm input)
__device__ int     g_hist[MAXN + 1];
__device__ int     g_rowptr[MAXN + 1];
__device__ int     g_cursor[MAXN];
__device__ int2    g_edge[MAXE];              // {src*32 (half2 base), coef bits}
__device__ float   g_dis[MAXN];
__device__ int     g_bcnt[GMAX];
__device__ int     g_tilectr;
__device__ unsigned long long g_tilestate[NTILES];
__device__ unsigned g_ctr = 0;
__device__ unsigned g_gen = 0;

// ---- grid-wide barrier: atomic arrive, volatile-load spin ------------------------------
__device__ __forceinline__ void gridbar(unsigned nb) {
    __syncthreads();
    if (threadIdx.x == 0) {
        __threadfence();
        volatile unsigned* genp = &g_gen;
        unsigned gen = *genp;
        unsigned t = atomicAdd(&g_ctr, 1u);
        if (t == nb - 1u) {
            atomicExch(&g_ctr, 0u);
            __threadfence();
            atomicAdd(&g_gen, 1u);
        } else {
            while (*genp == gen) __nanosleep(64);
        }
        __threadfence();
    }
    __syncthreads();
}

// ---- aggregate: warp per node; all-fp16 operands, fp32 accumulate -----------------------
// Ah[v] = dis[v]^2 * Xh[v] + sum_in coef * Xh[src]
__device__ __forceinline__ void dev_agg(int n, int gtid, int gstride)
{
    int lane = gtid & 31;
    int w = gtid >> 5;
    int wstride = gstride >> 5;

    for (int node = w; node < n; node += wstride) {
        int e  = g_rowptr[node];
        int e1 = g_rowptr[node + 1];

        float ds = g_dis[node];
        float2 xv = __half22float2(g_Xh[(size_t)node * 32 + lane]);
        float s = ds * ds;
        float2 acc[4];
        acc[0] = make_float2(s * xv.x, s * xv.y);
        acc[1] = make_float2(0.f, 0.f);
        acc[2] = make_float2(0.f, 0.f);
        acc[3] = make_float2(0.f, 0.f);

        for (; e + 8 <= e1; e += 8) {
            int2 d[8]; __half2 h[8];
#pragma unroll
            for (int u = 0; u < 8; u++) d[u] = g_edge[e + u];
#pragma unroll
            for (int u = 0; u < 8; u++) h[u] = g_Xh[d[u].x + lane];
#pragma unroll
            for (int u = 0; u < 8; u++) {
                float c = __int_as_float(d[u].y);
                float2 f = __half22float2(h[u]);
                acc[u & 3].x += c * f.x;
                acc[u & 3].y += c * f.y;
            }
        }
        if (e + 4 <= e1) {
            int2 d[4]; __half2 h[4];
#pragma unroll
            for (int u = 0; u < 4; u++) d[u] = g_edge[e + u];
#pragma unroll
            for (int u = 0; u < 4; u++) h[u] = g_Xh[d[u].x + lane];
#pragma unroll
            for (int u = 0; u < 4; u++) {
                float c = __int_as_float(d[u].y);
                float2 f = __half22float2(h[u]);
                acc[u].x += c * f.x;
                acc[u].y += c * f.y;
            }
            e += 4;
        }
        for (; e < e1; e++) {
            int2 d0 = g_edge[e];
            float2 f = __half22float2(g_Xh[d0.x + lane]);
            float c = __int_as_float(d0.y);
            acc[0].x += c * f.x;
            acc[0].y += c * f.y;
        }

        float2 r;
        r.x = (acc[0].x + acc[1].x) + (acc[2].x + acc[3].x);
        r.y = (acc[0].y + acc[1].y) + (acc[2].y + acc[3].y);
        g_Ah[(size_t)node * 32 + lane] = __floats2half2_rn(r.x, r.y);
    }
}

// ---- GEMM tile phase: fp16 in (g_Ah), fp32 acc; out = fp16 Xh OR fp32 out_h(+pool) ------
__device__ __forceinline__ void dev_gemm(
    const float* __restrict__ W, const float* __restrict__ bias,
    const float* __restrict__ bg, const float* __restrict__ bbe,
    const float* __restrict__ brm, const float* __restrict__ brv,
    const int* __restrict__ batch,
    float* __restrict__ out, bool toXh, float* __restrict__ hg,
    int n, bool bn, bool relu, bool pool,
    int bid, int nb, float* xs, float* ws)
{
    int t = threadIdx.x;
    int ntiles = (n + 63) / 64;
    int i4 = t >> 4;
    int j4 = t & 15;

    for (int tb = bid; tb < ntiles; tb += nb) {
        int row0 = tb * 64;
        __syncthreads();

        const float4* W4 = (const float4*)W;
        float4* ws4 = (float4*)ws;
#pragma unroll
        for (int i = 0; i < 4; i++) ws4[t + i * 256] = W4[t + i * 256];

#pragma unroll
        for (int i = 0; i < 8; i++) {
            int idx = t + i * 256;
            int r = idx >> 5, c = idx & 31;
            float2 f = make_float2(0.f, 0.f);
            if (row0 + r < n) f = __half22float2(g_Ah[(size_t)(row0 + r) * 32 + c]);
            xs[r * 65 + c * 2 + 0] = f.x;
            xs[r * 65 + c * 2 + 1] = f.y;
        }
        __syncthreads();

        float acc[4][4];
#pragma unroll
        for (int a = 0; a < 4; a++)
#pragma unroll
            for (int c = 0; c < 4; c++) acc[a][c] = 0.f;

#pragma unroll
        for (int k = 0; k < 64; k++) {
            float4 b = *(const float4*)&ws[k * 64 + j4 * 4];
            float a0 = xs[(i4 * 4 + 0) * 65 + k];
            float a1 = xs[(i4 * 4 + 1) * 65 + k];
            float a2 = xs[(i4 * 4 + 2) * 65 + k];
            float a3 = xs[(i4 * 4 + 3) * 65 + k];
            acc[0][0] += a0 * b.x; acc[0][1] += a0 * b.y; acc[0][2] += a0 * b.z; acc[0][3] += a0 * b.w;
            acc[1][0] += a1 * b.x; acc[1][1] += a1 * b.y; acc[1][2] += a1 * b.z; acc[1][3] += a1 * b.w;
            acc[2][0] += a2 * b.x; acc[2][1] += a2 * b.y; acc[2][2] += a2 * b.z; acc[2][3] += a2 * b.w;
            acc[3][0] += a3 * b.x; acc[3][1] += a3 * b.y; acc[3][2] += a3 * b.z; acc[3][3] += a3 * b.w;
        }

        float4 bb = *(const float4*)&bias[j4 * 4];
        float4 sc = make_float4(0.f, 0.f, 0.f, 0.f);
        float4 rm = make_float4(0.f, 0.f, 0.f, 0.f);
        float4 be = make_float4(0.f, 0.f, 0.f, 0.f);
        if (bn) {
            float4 gv = *(const float4*)&bg[j4 * 4];
            float4 rv = *(const float4*)&brv[j4 * 4];
            rm = *(const float4*)&brm[j4 * 4];
            be = *(const float4*)&bbe[j4 * 4];
            sc.x = gv.x * rsqrtf(rv.x + EPS);
            sc.y = gv.y * rsqrtf(rv.y + EPS);
            sc.z = gv.z * rsqrtf(rv.z + EPS);
            sc.w = gv.w * rsqrtf(rv.w + EPS);
        }

#pragma unroll
        for (int ii = 0; ii < 4; ii++) {
            int gr = row0 + i4 * 4 + ii;
            if (gr < n) {
                float4 v = make_float4(acc[ii][0] + bb.x, acc[ii][1] + bb.y,
                                       acc[ii][2] + bb.z, acc[ii][3] + bb.w);
                if (bn) {
                    v.x = (v.x - rm.x) * sc.x + be.x;
                    v.y = (v.y - rm.y) * sc.y + be.y;
                    v.z = (v.z - rm.z) * sc.z + be.z;
                    v.w = (v.w - rm.w) * sc.w + be.w;
                }
                if (relu) {
                    v.x = fmaxf(v.x, 0.f); v.y = fmaxf(v.y, 0.f);
                    v.z = fmaxf(v.z, 0.f); v.w = fmaxf(v.w, 0.f);
                }
                if (toXh) {
                    g_Xh[(size_t)gr * 32 + j4 * 2 + 0] = __floats2half2_rn(v.x, v.y);
                    g_Xh[(size_t)gr * 32 + j4 * 2 + 1] = __floats2half2_rn(v.z, v.w);
                } else {
                    *(float4*)&out[(size_t)gr * 64 + j4 * 4] = v;
                }
                if (pool) {
                    int g = batch[gr];
                    float ic = 1.f / fmaxf((float)g_bcnt[g], 1.f);
                    float* h = &hg[g * 64 + j4 * 4];
                    atomicAdd(&h[0], v.x * ic);
                    atomicAdd(&h[1], v.y * ic);
                    atomicAdd(&h[2], v.z * ic);
                    atomicAdd(&h[3], v.w * ic);
                }
            }
        }
        __syncthreads();
    }
}

// ---- the single persistent kernel ---------------------------------------------------------
__global__ void __launch_bounds__(TPB, 4) k_persist(
    const float* __restrict__ x,
    const int* __restrict__ src, const int* __restrict__ dstp,
    const int* __restrict__ batch,
    const float* __restrict__ W1, const float* __restrict__ b1,
    const float* __restrict__ W2, const float* __restrict__ b2,
    const float* __restrict__ W3, const float* __restrict__ b3,
    const float* __restrict__ g1, const float* __restrict__ be1,
    const float* __restrict__ rm1, const float* __restrict__ rv1,
    const float* __restrict__ g2, const float* __restrict__ be2,
    const float* __restrict__ rm2, const float* __restrict__ rv2,
    float* __restrict__ out_h, float* __restrict__ out_hg,
    int n, int e, int gtot)
{
    __shared__ float s_buf[64 * 65 + 64 * 64];
    unsigned nb = gridDim.x;
    int bid = blockIdx.x, tid = threadIdx.x;
    int gtid = bid * TPB + tid;
    int gstride = nb * TPB;
    int* si = (int*)s_buf;
    __shared__ int s_tile, s_prefix;

    // P1: degree histogram + fp16-stage x + zero pool buffers
    for (int i = gtid; i < e; i += gstride) atomicAdd(&g_hist[dstp[i]], 1);
    {
        const float2* X2 = (const float2*)x;
        for (int i = gtid; i < n * 32; i += gstride) {
            float2 f = X2[i];
            g_Xh[i] = __floats2half2_rn(f.x, f.y);
        }
    }
    for (int i = gtid; i < gtot * D; i += gstride) out_hg[i] = 0.f;
    for (int i = gtid; i < gtot; i += gstride) g_bcnt[i] = 0;
    gridbar(nb);

    // P2: single-pass decoupled-lookback scan; rowptr/cursor/dis, re-zero hist
    int nchunks = (n + TPB - 1) / TPB;
    while (true) {
        if (tid == 0) s_tile = atomicAdd(&g_tilectr, 1);
        __syncthreads();
        int t = s_tile;
        if (t >= nchunks) break;
        int base = t * TPB + tid;
        int v = 0;
        if (base < n) {
            v = g_hist[base];
            g_hist[base] = 0;
            g_dis[base] = rsqrtf((float)v + 1.0f);
        }
        si[tid] = v;
        __syncthreads();
        for (int off = 1; off < 256; off <<= 1) {
            int u = (tid >= off) ? si[tid - off] : 0;
            __syncthreads();
            si[tid] += u;
            __syncthreads();
        }
        int incl = si[tid];
        int bsum = si[255];
        if (tid == 0) {
            unsigned long long pack = t == 0 ? ((2ULL << 32) | (unsigned)bsum)
                                             : ((1ULL << 32) | (unsigned)bsum);
            atomicExch(&g_tilestate[t], pack);
            int pref = 0;
            if (t > 0) {
                int j = t - 1;
                while (true) {
                    unsigned long long st = atomicAdd(&g_tilestate[j], 0ULL);
                    unsigned flag = (unsigned)(st >> 32);
                    if (flag == 2) { pref += (int)(unsigned)st; break; }
                    if (flag == 1) { pref += (int)(unsigned)st; j--; continue; }
                    __nanosleep(40);
                }
                atomicExch(&g_tilestate[t], (2ULL << 32) | (unsigned)(pref + bsum));
            }
            s_prefix = pref;
        }
        __syncthreads();
        int ex = s_prefix + incl - v;
        if (base < n) { g_rowptr[base] = ex; g_cursor[base] = ex; }
        if (base == n - 1) g_rowptr[n] = ex + v;
        __syncthreads();
    }
    gridbar(nb);

    // P3: CSR fill (pre-shifted src) + batch counts + reset scan state
    for (int i = gtid; i < e; i += gstride) {
        int s = src[i], d = dstp[i];
        int pos = atomicAdd(&g_cursor[d], 1);
        float c = g_dis[s] * g_dis[d];
        g_edge[pos] = make_int2(s << 5, __float_as_int(c));
    }
    for (int i = gtid; i < n; i += gstride) atomicAdd(&g_bcnt[batch[i]], 1);
    if (gtid < NTILES) g_tilestate[gtid] = 0ULL;
    if (gtid == 0) g_tilectr = 0;
    gridbar(nb);

    float* xs = s_buf;
    float* ws = s_buf + 64 * 65;

    // ======== MEASUREMENT ROUND: each agg phase runs TWICE (idempotent) ========
    // dur delta vs R12 = 3 x (one agg phase). Results identical; benign same-value
    // write overlap between the duplicate passes.

    // layer 1
    dev_agg(n, gtid, gstride);
    dev_agg(n, gtid, gstride);          // duplicate (probe)
    gridbar(nb);
    dev_gemm(W1, b1, g1, be1, rm1, rv1, nullptr, nullptr, true, nullptr,
             n, true, true, false, bid, nb, xs, ws);
    gridbar(nb);
    // layer 2
    dev_agg(n, gtid, gstride);
    dev_agg(n, gtid, gstride);          // duplicate (probe)
    gridbar(nb);
    dev_gemm(W2, b2, g2, be2, rm2, rv2, nullptr, nullptr, true, nullptr,
             n, true, true, false, bid, nb, xs, ws);
    gridbar(nb);
    // layer 3 + fused pool
    dev_agg(n, gtid, gstride);
    dev_agg(n, gtid, gstride);          // duplicate (probe)
    gridbar(nb);
    dev_gemm(W3, b3, nullptr, nullptr, nullptr, nullptr, batch, out_h, false, out_hg,
             n, false, false, true, bid, nb, xs, ws);
}

// ---- launch ---------------------------------------------------------------------------------
extern "C" void kernel_launch(void* const* d_in, const int* in_sizes, int n_in,
                              void* d_out, int out_size)
{
    const float* x    = (const float*)d_in[0];
    const int*   ei   = (const int*)d_in[1];
    const int*   batch= (const int*)d_in[2];

    const float *W1, *W2, *W3, *b1, *b2, *b3;
    if (in_sizes[4] == D * D) {
        W1 = (const float*)d_in[3]; W2 = (const float*)d_in[4]; W3 = (const float*)d_in[5];
        b1 = (const float*)d_in[6]; b2 = (const float*)d_in[7]; b3 = (const float*)d_in[8];
    } else {
        W1 = (const float*)d_in[3]; b1 = (const float*)d_in[4];
        W2 = (const float*)d_in[5]; b2 = (const float*)d_in[6];
        W3 = (const float*)d_in[7]; b3 = (const float*)d_in[8];
    }
    const float* g1   = (const float*)d_in[9];
    const float* be1  = (const float*)d_in[10];
    const float* rm1  = (const float*)d_in[11];
    const float* rv1  = (const float*)d_in[12];
    const float* g2   = (const float*)d_in[13];
    const float* be2  = (const float*)d_in[14];
    const float* rm2  = (const float*)d_in[15];
    const float* rv2  = (const float*)d_in[16];

    int n = in_sizes[0] / D;
    int e = in_sizes[1] / 2;
    int gtot = (out_size - n * D) / D;

    const int* src = ei;
    const int* dst = ei + e;

    float* out_h  = (float*)d_out;
    float* out_hg = (float*)d_out + (size_t)n * D;

    int dev = 0, nsm = 148;
    cudaGetDevice(&dev);
    cudaDeviceGetAttribute(&nsm, cudaDevAttrMultiProcessorCount, dev);
    int maxb = 1;
    cudaOccupancyMaxActiveBlocksPerMultiprocessor(&maxb, k_persist, TPB, 0);
    if (maxb < 1) maxb = 1;
    int grid = nsm * maxb;

    k_persist<<<grid, TPB>>>(x, src, dst, batch,
                             W1, b1, W2, b2, W3, b3,
                             g1, be1, rm1, rv1, g2, be2, rm2, rv2,
                             out_h, out_hg, n, e, gtot);
}

// round 14
// speedup vs baseline: 1.8831x; 1.8831x over previous
#include <cuda_runtime.h>
#include <cuda_fp16.h>

#define D 64
#define MAXN 100000
#define MAXE 1200000
#define GMAX 64
#define EPS 1e-5f
#define TPB 256
#define NTILES 512

__device__ __half2 g_Xh[(size_t)MAXN * 32];   // agg input  (gemm output / staged x)
__device__ __half2 g_Ah[(size_t)MAXN * 32];   // agg output (gemm input)
__device__ int     g_hist[MAXN + 1];
__device__ int     g_rowptr[MAXN + 1];
__device__ int     g_cursor[MAXN];
__device__ int2    g_edge[MAXE];              // {src*32 (half2 base), coef bits}
__device__ float   g_dis[MAXN];
__device__ int     g_bcnt[GMAX];
__device__ int     g_tilectr;
__device__ unsigned long long g_tilestate[NTILES];
__device__ unsigned g_ctr = 0;
__device__ unsigned g_gen = 0;

// ---- grid-wide barrier: atomic arrive, volatile-load spin ------------------------------
__device__ __forceinline__ void gridbar(unsigned nb) {
    __syncthreads();
    if (threadIdx.x == 0) {
        __threadfence();
        volatile unsigned* genp = &g_gen;
        unsigned gen = *genp;
        unsigned t = atomicAdd(&g_ctr, 1u);
        if (t == nb - 1u) {
            atomicExch(&g_ctr, 0u);
            __threadfence();
            atomicAdd(&g_gen, 1u);
        } else {
            while (*genp == gen) __nanosleep(64);
        }
        __threadfence();
    }
    __syncthreads();
}

// ---- aggregate: warp per node; all-fp16 operands, fp32 accumulate -----------------------
// Ah[v] = dis[v]^2 * Xh[v] + sum_in coef * Xh[src]
__device__ __forceinline__ void dev_agg(int n, int gtid, int gstride)
{
    int lane = gtid & 31;
    int w = gtid >> 5;
    int wstride = gstride >> 5;

    for (int node = w; node < n; node += wstride) {
        int e  = g_rowptr[node];
        int e1 = g_rowptr[node + 1];

        float ds = g_dis[node];
        float2 xv = __half22float2(g_Xh[(size_t)node * 32 + lane]);
        float s = ds * ds;
        float2 acc[4];
        acc[0] = make_float2(s * xv.x, s * xv.y);
        acc[1] = make_float2(0.f, 0.f);
        acc[2] = make_float2(0.f, 0.f);
        acc[3] = make_float2(0.f, 0.f);

        for (; e + 8 <= e1; e += 8) {
            int2 d[8]; __half2 h[8];
#pragma unroll
            for (int u = 0; u < 8; u++) d[u] = g_edge[e + u];
#pragma unroll
            for (int u = 0; u < 8; u++) h[u] = g_Xh[d[u].x + lane];
#pragma unroll
            for (int u = 0; u < 8; u++) {
                float c = __int_as_float(d[u].y);
                float2 f = __half22float2(h[u]);
                acc[u & 3].x += c * f.x;
                acc[u & 3].y += c * f.y;
            }
        }
        if (e + 4 <= e1) {
            int2 d[4]; __half2 h[4];
#pragma unroll
            for (int u = 0; u < 4; u++) d[u] = g_edge[e + u];
#pragma unroll
            for (int u = 0; u < 4; u++) h[u] = g_Xh[d[u].x + lane];
#pragma unroll
            for (int u = 0; u < 4; u++) {
                float c = __int_as_float(d[u].y);
                float2 f = __half22float2(h[u]);
                acc[u].x += c * f.x;
                acc[u].y += c * f.y;
            }
            e += 4;
        }
        for (; e < e1; e++) {
            int2 d0 = g_edge[e];
            float2 f = __half22float2(g_Xh[d0.x + lane]);
            float c = __int_as_float(d0.y);
            acc[0].x += c * f.x;
            acc[0].y += c * f.y;
        }

        float2 r;
        r.x = (acc[0].x + acc[1].x) + (acc[2].x + acc[3].x);
        r.y = (acc[0].y + acc[1].y) + (acc[2].y + acc[3].y);
        g_Ah[(size_t)node * 32 + lane] = __floats2half2_rn(r.x, r.y);
    }
}

// ---- GEMM tile phase: fp16 in (g_Ah), fp32 acc; out = fp16 Xh OR fp32 out_h(+pool) ------
__device__ __forceinline__ void dev_gemm(
    const float* __restrict__ W, const float* __restrict__ bias,
    const float* __restrict__ bg, const float* __restrict__ bbe,
    const float* __restrict__ brm, const float* __restrict__ brv,
    const int* __restrict__ batch,
    float* __restrict__ out, bool toXh, float* __restrict__ hg,
    int n, bool bn, bool relu, bool pool,
    int bid, int nb, float* xs, float* ws)
{
    int t = threadIdx.x;
    int ntiles = (n + 63) / 64;
    int i4 = t >> 4;
    int j4 = t & 15;

    for (int tb = bid; tb < ntiles; tb += nb) {
        int row0 = tb * 64;
        __syncthreads();

        const float4* W4 = (const float4*)W;
        float4* ws4 = (float4*)ws;
#pragma unroll
        for (int i = 0; i < 4; i++) ws4[t + i * 256] = W4[t + i * 256];

#pragma unroll
        for (int i = 0; i < 8; i++) {
            int idx = t + i * 256;
            int r = idx >> 5, c = idx & 31;
            float2 f = make_float2(0.f, 0.f);
            if (row0 + r < n) f = __half22float2(g_Ah[(size_t)(row0 + r) * 32 + c]);
            xs[r * 65 + c * 2 + 0] = f.x;
            xs[r * 65 + c * 2 + 1] = f.y;
        }
        __syncthreads();

        float acc[4][4];
#pragma unroll
        for (int a = 0; a < 4; a++)
#pragma unroll
            for (int c = 0; c < 4; c++) acc[a][c] = 0.f;

#pragma unroll
        for (int k = 0; k < 64; k++) {
            float4 b = *(const float4*)&ws[k * 64 + j4 * 4];
            float a0 = xs[(i4 * 4 + 0) * 65 + k];
            float a1 = xs[(i4 * 4 + 1) * 65 + k];
            float a2 = xs[(i4 * 4 + 2) * 65 + k];
            float a3 = xs[(i4 * 4 + 3) * 65 + k];
            acc[0][0] += a0 * b.x; acc[0][1] += a0 * b.y; acc[0][2] += a0 * b.z; acc[0][3] += a0 * b.w;
            acc[1][0] += a1 * b.x; acc[1][1] += a1 * b.y; acc[1][2] += a1 * b.z; acc[1][3] += a1 * b.w;
            acc[2][0] += a2 * b.x; acc[2][1] += a2 * b.y; acc[2][2] += a2 * b.z; acc[2][3] += a2 * b.w;
            acc[3][0] += a3 * b.x; acc[3][1] += a3 * b.y; acc[3][2] += a3 * b.z; acc[3][3] += a3 * b.w;
        }

        float4 bb = *(const float4*)&bias[j4 * 4];
        float4 sc = make_float4(0.f, 0.f, 0.f, 0.f);
        float4 rm = make_float4(0.f, 0.f, 0.f, 0.f);
        float4 be = make_float4(0.f, 0.f, 0.f, 0.f);
        if (bn) {
            float4 gv = *(const float4*)&bg[j4 * 4];
            float4 rv = *(const float4*)&brv[j4 * 4];
            rm = *(const float4*)&brm[j4 * 4];
            be = *(const float4*)&bbe[j4 * 4];
            sc.x = gv.x * rsqrtf(rv.x + EPS);
            sc.y = gv.y * rsqrtf(rv.y + EPS);
            sc.z = gv.z * rsqrtf(rv.z + EPS);
            sc.w = gv.w * rsqrtf(rv.w + EPS);
        }

        // pool fast path: whole tile within one graph (batch sorted)?
        bool singleG = false;
        int gTile = 0;
        if (pool) {
            int lastRow = row0 + 63;
            if (lastRow < n) {
                gTile = batch[row0];
                singleG = (batch[lastRow] == gTile);
            }
        }
        float4 psum = make_float4(0.f, 0.f, 0.f, 0.f);

#pragma unroll
        for (int ii = 0; ii < 4; ii++) {
            int gr = row0 + i4 * 4 + ii;
            if (gr < n) {
                float4 v = make_float4(acc[ii][0] + bb.x, acc[ii][1] + bb.y,
                                       acc[ii][2] + bb.z, acc[ii][3] + bb.w);
                if (bn) {
                    v.x = (v.x - rm.x) * sc.x + be.x;
                    v.y = (v.y - rm.y) * sc.y + be.y;
                    v.z = (v.z - rm.z) * sc.z + be.z;
                    v.w = (v.w - rm.w) * sc.w + be.w;
                }
                if (relu) {
                    v.x = fmaxf(v.x, 0.f); v.y = fmaxf(v.y, 0.f);
                    v.z = fmaxf(v.z, 0.f); v.w = fmaxf(v.w, 0.f);
                }
                if (toXh) {
                    g_Xh[(size_t)gr * 32 + j4 * 2 + 0] = __floats2half2_rn(v.x, v.y);
                    g_Xh[(size_t)gr * 32 + j4 * 2 + 1] = __floats2half2_rn(v.z, v.w);
                } else {
                    *(float4*)&out[(size_t)gr * 64 + j4 * 4] = v;
                }
                if (pool) {
                    if (singleG) {
                        psum.x += v.x; psum.y += v.y; psum.z += v.z; psum.w += v.w;
                    } else {
                        int g = batch[gr];
                        float ic = 1.f / fmaxf((float)g_bcnt[g], 1.f);
                        float* h = &hg[g * 64 + j4 * 4];
                        atomicAdd(&h[0], v.x * ic);
                        atomicAdd(&h[1], v.y * ic);
                        atomicAdd(&h[2], v.z * ic);
                        atomicAdd(&h[3], v.w * ic);
                    }
                }
            }
        }

        if (pool && singleG) {
            __syncthreads();                      // all threads done reading ws (k-loop)
            *(float4*)&ws[t * 4] = psum;          // stash per-thread partials
            __syncthreads();
            if (t < 64) {
                int jj = t >> 2, comp = t & 3;    // column t = jj*4 + comp
                float s = 0.f;
#pragma unroll
                for (int iv = 0; iv < 16; iv++)
                    s += ws[(iv * 16 + jj) * 4 + comp];
                float ic = 1.f / fmaxf((float)g_bcnt[gTile], 1.f);
                atomicAdd(&hg[gTile * 64 + t], s * ic);
            }
        }
        __syncthreads();
    }
}

// ---- the single persistent kernel ---------------------------------------------------------
__global__ void __launch_bounds__(TPB, 4) k_persist(
    const float* __restrict__ x,
    const int* __restrict__ src, const int* __restrict__ dstp,
    const int* __restrict__ batch,
    const float* __restrict__ W1, const float* __restrict__ b1,
    const float* __restrict__ W2, const float* __restrict__ b2,
    const float* __restrict__ W3, const float* __restrict__ b3,
    const float* __restrict__ g1, const float* __restrict__ be1,
    const float* __restrict__ rm1, const float* __restrict__ rv1,
    const float* __restrict__ g2, const float* __restrict__ be2,
    const float* __restrict__ rm2, const float* __restrict__ rv2,
    float* __restrict__ out_h, float* __restrict__ out_hg,
    int n, int e, int gtot)
{
    __shared__ float s_buf[64 * 65 + 64 * 64];
    unsigned nb = gridDim.x;
    int bid = blockIdx.x, tid = threadIdx.x;
    int gtid = bid * TPB + tid;
    int gstride = nb * TPB;
    int* si = (int*)s_buf;
    __shared__ int s_tile, s_prefix;

    // P1: degree histogram + fp16-stage x + zero pool buffers
    for (int i = gtid; i < e; i += gstride) atomicAdd(&g_hist[dstp[i]], 1);
    {
        const float2* X2 = (const float2*)x;
        for (int i = gtid; i < n * 32; i += gstride) {
            float2 f = X2[i];
            g_Xh[i] = __floats2half2_rn(f.x, f.y);
        }
    }
    for (int i = gtid; i < gtot * D; i += gstride) out_hg[i] = 0.f;
    for (int i = gtid; i < gtot; i += gstride) g_bcnt[i] = 0;
    gridbar(nb);

    // P2: single-pass decoupled-lookback scan; rowptr/cursor/dis, re-zero hist
    int nchunks = (n + TPB - 1) / TPB;
    while (true) {
        if (tid == 0) s_tile = atomicAdd(&g_tilectr, 1);
        __syncthreads();
        int t = s_tile;
        if (t >= nchunks) break;
        int base = t * TPB + tid;
        int v = 0;
        if (base < n) {
            v = g_hist[base];
            g_hist[base] = 0;
            g_dis[base] = rsqrtf((float)v + 1.0f);
        }
        si[tid] = v;
        __syncthreads();
        for (int off = 1; off < 256; off <<= 1) {
            int u = (tid >= off) ? si[tid - off] : 0;
            __syncthreads();
            si[tid] += u;
            __syncthreads();
        }
        int incl = si[tid];
        int bsum = si[255];
        if (tid == 0) {
            unsigned long long pack = t == 0 ? ((2ULL << 32) | (unsigned)bsum)
                                             : ((1ULL << 32) | (unsigned)bsum);
            atomicExch(&g_tilestate[t], pack);
            int pref = 0;
            if (t > 0) {
                int j = t - 1;
                while (true) {
                    unsigned long long st = atomicAdd(&g_tilestate[j], 0ULL);
                    unsigned flag = (unsigned)(st >> 32);
                    if (flag == 2) { pref += (int)(unsigned)st; break; }
                    if (flag == 1) { pref += (int)(unsigned)st; j--; continue; }
                    __nanosleep(40);
                }
                atomicExch(&g_tilestate[t], (2ULL << 32) | (unsigned)(pref + bsum));
            }
            s_prefix = pref;
        }
        __syncthreads();
        int ex = s_prefix + incl - v;
        if (base < n) { g_rowptr[base] = ex; g_cursor[base] = ex; }
        if (base == n - 1) g_rowptr[n] = ex + v;
        __syncthreads();
    }
    gridbar(nb);

    // P3: CSR fill (pre-shifted src) + batch counts + reset scan state
    for (int i = gtid; i < e; i += gstride) {
        int s = src[i], d = dstp[i];
        int pos = atomicAdd(&g_cursor[d], 1);
        float c = g_dis[s] * g_dis[d];
        g_edge[pos] = make_int2(s << 5, __float_as_int(c));
    }
    for (int i = gtid; i < n; i += gstride) atomicAdd(&g_bcnt[batch[i]], 1);
    if (gtid < NTILES) g_tilestate[gtid] = 0ULL;
    if (gtid == 0) g_tilectr = 0;
    gridbar(nb);

    float* xs = s_buf;
    float* ws = s_buf + 64 * 65;

    // layer 1
    dev_agg(n, gtid, gstride);
    gridbar(nb);
    dev_gemm(W1, b1, g1, be1, rm1, rv1, nullptr, nullptr, true, nullptr,
             n, true, true, false, bid, nb, xs, ws);
    gridbar(nb);
    // layer 2
    dev_agg(n, gtid, gstride);
    gridbar(nb);
    dev_gemm(W2, b2, g2, be2, rm2, rv2, nullptr, nullptr, true, nullptr,
             n, true, true, false, bid, nb, xs, ws);
    gridbar(nb);
    // layer 3 + fused pool (fp32 output)
    dev_agg(n, gtid, gstride);
    gridbar(nb);
    dev_gemm(W3, b3, nullptr, nullptr, nullptr, nullptr, batch, out_h, false, out_hg,
             n, false, false, true, bid, nb, xs, ws);
}

// ---- launch ---------------------------------------------------------------------------------
extern "C" void kernel_launch(void* const* d_in, const int* in_sizes, int n_in,
                              void* d_out, int out_size)
{
    const float* x    = (const float*)d_in[0];
    const int*   ei   = (const int*)d_in[1];
    const int*   batch= (const int*)d_in[2];

    const float *W1, *W2, *W3, *b1, *b2, *b3;
    if (in_sizes[4] == D * D) {
        W1 = (const float*)d_in[3]; W2 = (const float*)d_in[4]; W3 = (const float*)d_in[5];
        b1 = (const float*)d_in[6]; b2 = (const float*)d_in[7]; b3 = (const float*)d_in[8];
    } else {
        W1 = (const float*)d_in[3]; b1 = (const float*)d_in[4];
        W2 = (const float*)d_in[5]; b2 = (const float*)d_in[6];
        W3 = (const float*)d_in[7]; b3 = (const float*)d_in[8];
    }
    const float* g1   = (const float*)d_in[9];
    const float* be1  = (const float*)d_in[10];
    const float* rm1  = (const float*)d_in[11];
    const float* rv1  = (const float*)d_in[12];
    const float* g2   = (const float*)d_in[13];
    const float* be2  = (const float*)d_in[14];
    const float* rm2  = (const float*)d_in[15];
    const float* rv2  = (const float*)d_in[16];

    int n = in_sizes[0] / D;
    int e = in_sizes[1] / 2;
    int gtot = (out_size - n * D) / D;

    const int* src = ei;
    const int* dst = ei + e;

    float* out_h  = (float*)d_out;
    float* out_hg = (float*)d_out + (size_t)n * D;

    int dev = 0, nsm = 148;
    cudaGetDevice(&dev);
    cudaDeviceGetAttribute(&nsm, cudaDevAttrMultiProcessorCount, dev);
    int maxb = 1;
    cudaOccupancyMaxActiveBlocksPerMultiprocessor(&maxb, k_persist, TPB, 0);
    if (maxb < 1) maxb = 1;
    int grid = nsm * maxb;

    k_persist<<<grid, TPB>>>(x, src, dst, batch,
                             W1, b1, W2, b2, W3, b3,
                             g1, be1, rm1, rv1, g2, be2, rm2, rv2,
                             out_h, out_hg, n, e, gtot);
}

// round 15
// speedup vs baseline: 1.9499x; 1.0354x over previous
#include <cuda_runtime.h>
#include <cuda_fp16.h>

#define D 64
#define MAXN 100000
#define MAXE 1200000
#define GMAX 64
#define EPS 1e-5f
#define TPB 256
#define NTILES 512

__device__ __half2 g_XhA[(size_t)MAXN * 32];  // ping-pong fp16 feature buffers
__device__ __half2 g_XhB[(size_t)MAXN * 32];
__device__ int     g_hist[MAXN + 1];
__device__ int     g_rowptr[MAXN + 1];
__device__ int     g_cursor[MAXN];
__device__ int2    g_edge[MAXE];              // {src*32 (half2 base), coef bits}
__device__ float   g_dis[MAXN];
__device__ int     g_bcnt[GMAX];
__device__ int     g_tilectr;
__device__ unsigned long long g_tilestate[NTILES];
__device__ unsigned g_ctr = 0;
__device__ unsigned g_gen = 0;

// ---- grid-wide barrier: atomic arrive, volatile-load spin ------------------------------
__device__ __forceinline__ void gridbar(unsigned nb) {
    __syncthreads();
    if (threadIdx.x == 0) {
        __threadfence();
        volatile unsigned* genp = &g_gen;
        unsigned gen = *genp;
        unsigned t = atomicAdd(&g_ctr, 1u);
        if (t == nb - 1u) {
            atomicExch(&g_ctr, 0u);
            __threadfence();
            atomicAdd(&g_gen, 1u);
        } else {
            while (*genp == gen) __nanosleep(64);
        }
        __threadfence();
    }
    __syncthreads();
}

// ---- fused layer: per tile, aggregate 64 nodes into smem, then GEMM the tile ------------
// agg:  xs[r] = dis^2 * Xin[node] + sum coef * Xin[src]      (fp32 in smem)
// gemm: out-tile = xs @ W + b [,BN][,ReLU]; write Xout fp16 or out fp32 (+pool)
__device__ __forceinline__ void dev_layer(
    const __half2* __restrict__ Xin, __half2* __restrict__ Xout,
    const float* __restrict__ W, const float* __restrict__ bias,
    const float* __restrict__ bg, const float* __restrict__ bbe,
    const float* __restrict__ brm, const float* __restrict__ brv,
    const int* __restrict__ batch,
    float* __restrict__ out, float* __restrict__ hg,
    int n, bool bn, bool relu, bool pool,
    int bid, int nb, float* xs, float* ws)
{
    int t = threadIdx.x;
    int lane = t & 31;
    int w = t >> 5;
    int ntiles = (n + 63) / 64;
    int i4 = t >> 4;
    int j4 = t & 15;

    // load W once per layer (loop-top syncthreads makes it visible before use)
    const float4* W4 = (const float4*)W;
    float4* ws4 = (float4*)ws;
#pragma unroll
    for (int i = 0; i < 4; i++) ws4[t + i * 256] = W4[t + i * 256];

    for (int tb = bid; tb < ntiles; tb += nb) {
        int row0 = tb * 64;
        __syncthreads();   // xs reuse + W visibility (first iter)

        // ---- aggregate: warp w handles rows w*8 .. w*8+7 ----
#pragma unroll 1
        for (int rr = 0; rr < 8; rr++) {
            int r = w * 8 + rr;
            int node = row0 + r;
            float2 res = make_float2(0.f, 0.f);
            if (node < n) {
                int e  = g_rowptr[node];
                int e1 = g_rowptr[node + 1];
                float ds = g_dis[node];
                float2 xv = __half22float2(Xin[(size_t)node * 32 + lane]);
                float s = ds * ds;
                float2 acc[4];
                acc[0] = make_float2(s * xv.x, s * xv.y);
                acc[1] = make_float2(0.f, 0.f);
                acc[2] = make_float2(0.f, 0.f);
                acc[3] = make_float2(0.f, 0.f);

                for (; e + 8 <= e1; e += 8) {
                    int2 d[8]; __half2 h[8];
#pragma unroll
                    for (int u = 0; u < 8; u++) d[u] = g_edge[e + u];
#pragma unroll
                    for (int u = 0; u < 8; u++) h[u] = Xin[d[u].x + lane];
#pragma unroll
                    for (int u = 0; u < 8; u++) {
                        float c = __int_as_float(d[u].y);
                        float2 f = __half22float2(h[u]);
                        acc[u & 3].x += c * f.x;
                        acc[u & 3].y += c * f.y;
                    }
                }
                if (e + 4 <= e1) {
                    int2 d[4]; __half2 h[4];
#pragma unroll
                    for (int u = 0; u < 4; u++) d[u] = g_edge[e + u];
#pragma unroll
                    for (int u = 0; u < 4; u++) h[u] = Xin[d[u].x + lane];
#pragma unroll
                    for (int u = 0; u < 4; u++) {
                        float c = __int_as_float(d[u].y);
                        float2 f = __half22float2(h[u]);
                        acc[u].x += c * f.x;
                        acc[u].y += c * f.y;
                    }
                    e += 4;
                }
                for (; e < e1; e++) {
                    int2 d0 = g_edge[e];
                    float2 f = __half22float2(Xin[d0.x + lane]);
                    float c = __int_as_float(d0.y);
                    acc[0].x += c * f.x;
                    acc[0].y += c * f.y;
                }
                res.x = (acc[0].x + acc[1].x) + (acc[2].x + acc[3].x);
                res.y = (acc[0].y + acc[1].y) + (acc[2].y + acc[3].y);
            }
            xs[r * 65 + lane * 2 + 0] = res.x;
            xs[r * 65 + lane * 2 + 1] = res.y;
        }
        __syncthreads();

        // ---- GEMM on the tile ----
        float acc[4][4];
#pragma unroll
        for (int a = 0; a < 4; a++)
#pragma unroll
            for (int c = 0; c < 4; c++) acc[a][c] = 0.f;

#pragma unroll
        for (int k = 0; k < 64; k++) {
            float4 b = *(const float4*)&ws[k * 64 + j4 * 4];
            float a0 = xs[(i4 * 4 + 0) * 65 + k];
            float a1 = xs[(i4 * 4 + 1) * 65 + k];
            float a2 = xs[(i4 * 4 + 2) * 65 + k];
            float a3 = xs[(i4 * 4 + 3) * 65 + k];
            acc[0][0] += a0 * b.x; acc[0][1] += a0 * b.y; acc[0][2] += a0 * b.z; acc[0][3] += a0 * b.w;
            acc[1][0] += a1 * b.x; acc[1][1] += a1 * b.y; acc[1][2] += a1 * b.z; acc[1][3] += a1 * b.w;
            acc[2][0] += a2 * b.x; acc[2][1] += a2 * b.y; acc[2][2] += a2 * b.z; acc[2][3] += a2 * b.w;
            acc[3][0] += a3 * b.x; acc[3][1] += a3 * b.y; acc[3][2] += a3 * b.z; acc[3][3] += a3 * b.w;
        }

        float4 bb = *(const float4*)&bias[j4 * 4];
        float4 sc = make_float4(0.f, 0.f, 0.f, 0.f);
        float4 rm = make_float4(0.f, 0.f, 0.f, 0.f);
        float4 be = make_float4(0.f, 0.f, 0.f, 0.f);
        if (bn) {
            float4 gv = *(const float4*)&bg[j4 * 4];
            float4 rv = *(const float4*)&brv[j4 * 4];
            rm = *(const float4*)&brm[j4 * 4];
            be = *(const float4*)&bbe[j4 * 4];
            sc.x = gv.x * rsqrtf(rv.x + EPS);
            sc.y = gv.y * rsqrtf(rv.y + EPS);
            sc.z = gv.z * rsqrtf(rv.z + EPS);
            sc.w = gv.w * rsqrtf(rv.w + EPS);
        }

        bool singleG = false;
        int gTile = 0;
        if (pool) {
            int lastRow = row0 + 63;
            if (lastRow < n) {
                gTile = batch[row0];
                singleG = (batch[lastRow] == gTile);
            }
        }
        float4 psum = make_float4(0.f, 0.f, 0.f, 0.f);

#pragma unroll
        for (int ii = 0; ii < 4; ii++) {
            int gr = row0 + i4 * 4 + ii;
            if (gr < n) {
                float4 v = make_float4(acc[ii][0] + bb.x, acc[ii][1] + bb.y,
                                       acc[ii][2] + bb.z, acc[ii][3] + bb.w);
                if (bn) {
                    v.x = (v.x - rm.x) * sc.x + be.x;
                    v.y = (v.y - rm.y) * sc.y + be.y;
                    v.z = (v.z - rm.z) * sc.z + be.z;
                    v.w = (v.w - rm.w) * sc.w + be.w;
                }
                if (relu) {
                    v.x = fmaxf(v.x, 0.f); v.y = fmaxf(v.y, 0.f);
                    v.z = fmaxf(v.z, 0.f); v.w = fmaxf(v.w, 0.f);
                }
                if (Xout) {
                    Xout[(size_t)gr * 32 + j4 * 2 + 0] = __floats2half2_rn(v.x, v.y);
                    Xout[(size_t)gr * 32 + j4 * 2 + 1] = __floats2half2_rn(v.z, v.w);
                } else {
                    *(float4*)&out[(size_t)gr * 64 + j4 * 4] = v;
                }
                if (pool) {
                    if (singleG) {
                        psum.x += v.x; psum.y += v.y; psum.z += v.z; psum.w += v.w;
                    } else {
                        int g = batch[gr];
                        float ic = 1.f / fmaxf((float)g_bcnt[g], 1.f);
                        float* h = &hg[g * 64 + j4 * 4];
                        atomicAdd(&h[0], v.x * ic);
                        atomicAdd(&h[1], v.y * ic);
                        atomicAdd(&h[2], v.z * ic);
                        atomicAdd(&h[3], v.w * ic);
                    }
                }
            }
        }

        if (pool && singleG) {
            __syncthreads();                       // all threads done reading xs
            *(float4*)&xs[t * 4] = psum;           // stash partials in xs (W in ws stays live)
            __syncthreads();
            if (t < 64) {
                int jj = t >> 2, comp = t & 3;
                float s = 0.f;
#pragma unroll
                for (int iv = 0; iv < 16; iv++)
                    s += xs[(iv * 16 + jj) * 4 + comp];
                float ic = 1.f / fmaxf((float)g_bcnt[gTile], 1.f);
                atomicAdd(&hg[gTile * 64 + t], s * ic);
            }
        }
    }
    __syncthreads();
}

// ---- the single persistent kernel ---------------------------------------------------------
__global__ void __launch_bounds__(TPB, 4) k_persist(
    const float* __restrict__ x,
    const int* __restrict__ src, const int* __restrict__ dstp,
    const int* __restrict__ batch,
    const float* __restrict__ W1, const float* __restrict__ b1,
    const float* __restrict__ W2, const float* __restrict__ b2,
    const float* __restrict__ W3, const float* __restrict__ b3,
    const float* __restrict__ g1, const float* __restrict__ be1,
    const float* __restrict__ rm1, const float* __restrict__ rv1,
    const float* __restrict__ g2, const float* __restrict__ be2,
    const float* __restrict__ rm2, const float* __restrict__ rv2,
    float* __restrict__ out_h, float* __restrict__ out_hg,
    int n, int e, int gtot)
{
    __shared__ float s_buf[64 * 65 + 64 * 64];
    unsigned nb = gridDim.x;
    int bid = blockIdx.x, tid = threadIdx.x;
    int gtid = bid * TPB + tid;
    int gstride = nb * TPB;
    int* si = (int*)s_buf;
    __shared__ int s_tile, s_prefix;

    // P1: degree histogram + fp16-stage x into XhA + zero pool buffers
    for (int i = gtid; i < e; i += gstride) atomicAdd(&g_hist[dstp[i]], 1);
    {
        const float2* X2 = (const float2*)x;
        for (int i = gtid; i < n * 32; i += gstride) {
            float2 f = X2[i];
            g_XhA[i] = __floats2half2_rn(f.x, f.y);
        }
    }
    for (int i = gtid; i < gtot * D; i += gstride) out_hg[i] = 0.f;
    for (int i = gtid; i < gtot; i += gstride) g_bcnt[i] = 0;
    gridbar(nb);

    // P2: single-pass decoupled-lookback scan; rowptr/cursor/dis, re-zero hist
    int nchunks = (n + TPB - 1) / TPB;
    while (true) {
        if (tid == 0) s_tile = atomicAdd(&g_tilectr, 1);
        __syncthreads();
        int t = s_tile;
        if (t >= nchunks) break;
        int base = t * TPB + tid;
        int v = 0;
        if (base < n) {
            v = g_hist[base];
            g_hist[base] = 0;
            g_dis[base] = rsqrtf((float)v + 1.0f);
        }
        si[tid] = v;
        __syncthreads();
        for (int off = 1; off < 256; off <<= 1) {
            int u = (tid >= off) ? si[tid - off] : 0;
            __syncthreads();
            si[tid] += u;
            __syncthreads();
        }
        int incl = si[tid];
        int bsum = si[255];
        if (tid == 0) {
            unsigned long long pack = t == 0 ? ((2ULL << 32) | (unsigned)bsum)
                                             : ((1ULL << 32) | (unsigned)bsum);
            atomicExch(&g_tilestate[t], pack);
            int pref = 0;
            if (t > 0) {
                int j = t - 1;
                while (true) {
                    unsigned long long st = atomicAdd(&g_tilestate[j], 0ULL);
                    unsigned flag = (unsigned)(st >> 32);
                    if (flag == 2) { pref += (int)(unsigned)st; break; }
                    if (flag == 1) { pref += (int)(unsigned)st; j--; continue; }
                    __nanosleep(40);
                }
                atomicExch(&g_tilestate[t], (2ULL << 32) | (unsigned)(pref + bsum));
            }
            s_prefix = pref;
        }
        __syncthreads();
        int ex = s_prefix + incl - v;
        if (base < n) { g_rowptr[base] = ex; g_cursor[base] = ex; }
        if (base == n - 1) g_rowptr[n] = ex + v;
        __syncthreads();
    }
    gridbar(nb);

    // P3: CSR fill (pre-shifted src) + batch counts + reset scan state
    for (int i = gtid; i < e; i += gstride) {
        int s = src[i], d = dstp[i];
        int pos = atomicAdd(&g_cursor[d], 1);
        float c = g_dis[s] * g_dis[d];
        g_edge[pos] = make_int2(s << 5, __float_as_int(c));
    }
    for (int i = gtid; i < n; i += gstride) atomicAdd(&g_bcnt[batch[i]], 1);
    if (gtid < NTILES) g_tilestate[gtid] = 0ULL;
    if (gtid == 0) g_tilectr = 0;
    gridbar(nb);

    float* xs = s_buf;
    float* ws = s_buf + 64 * 65;

    // layer 1: XhA -> XhB
    dev_layer(g_XhA, g_XhB, W1, b1, g1, be1, rm1, rv1, nullptr, nullptr, nullptr,
              n, true, true, false, bid, nb, xs, ws);
    gridbar(nb);
    // layer 2: XhB -> XhA
    dev_layer(g_XhB, g_XhA, W2, b2, g2, be2, rm2, rv2, nullptr, nullptr, nullptr,
              n, true, true, false, bid, nb, xs, ws);
    gridbar(nb);
    // layer 3: XhA -> fp32 out + fused pool
    dev_layer(g_XhA, nullptr, W3, b3, nullptr, nullptr, nullptr, nullptr, batch,
              out_h, out_hg, n, false, false, true, bid, nb, xs, ws);
}

// ---- launch ---------------------------------------------------------------------------------
extern "C" void kernel_launch(void* const* d_in, const int* in_sizes, int n_in,
                              void* d_out, int out_size)
{
    const float* x    = (const float*)d_in[0];
    const int*   ei   = (const int*)d_in[1];
    const int*   batch= (const int*)d_in[2];

    const float *W1, *W2, *W3, *b1, *b2, *b3;
    if (in_sizes[4] == D * D) {
        W1 = (const float*)d_in[3]; W2 = (const float*)d_in[4]; W3 = (const float*)d_in[5];
        b1 = (const float*)d_in[6]; b2 = (const float*)d_in[7]; b3 = (const float*)d_in[8];
    } else {
        W1 = (const float*)d_in[3]; b1 = (const float*)d_in[4];
        W2 = (const float*)d_in[5]; b2 = (const float*)d_in[6];
        W3 = (const float*)d_in[7]; b3 = (const float*)d_in[8];
    }
    const float* g1   = (const float*)d_in[9];
    const float* be1  = (const float*)d_in[10];
    const float* rm1  = (const float*)d_in[11];
    const float* rv1  = (const float*)d_in[12];
    const float* g2   = (const float*)d_in[13];
    const float* be2  = (const float*)d_in[14];
    const float* rm2  = (const float*)d_in[15];
    const float* rv2  = (const float*)d_in[16];

    int n = in_sizes[0] / D;
    int e = in_sizes[1] / 2;
    int gtot = (out_size - n * D) / D;

    const int* src = ei;
    const int* dst = ei + e;

    float* out_h  = (float*)d_out;
    float* out_hg = (float*)d_out + (size_t)n * D;

    int dev = 0, nsm = 148;
    cudaGetDevice(&dev);
    cudaDeviceGetAttribute(&nsm, cudaDevAttrMultiProcessorCount, dev);
    int maxb = 1;
    cudaOccupancyMaxActiveBlocksPerMultiprocessor(&maxb, k_persist, TPB, 0);
    if (maxb < 1) maxb = 1;
    int grid = nsm * maxb;

    k_persist<<<grid, TPB>>>(x, src, dst, batch,
                             W1, b1, W2, b2, W3, b3,
                             g1, be1, rm1, rv1, g2, be2, rm2, rv2,
                             out_h, out_hg, n, e, gtot);
}

// round 16
// speedup vs baseline: 1.9853x; 1.0182x over previous
#include <cuda_runtime.h>
#include <cuda_fp16.h>

#define D 64
#define MAXN 100000
#define MAXE 1200000
#define GMAX 64
#define EPS 1e-5f
#define TPB 256
#define NTILES 512

__device__ __half2 g_YhA[(size_t)MAXN * 32];  // ping-pong fp16 dis-scaled features
__device__ __half2 g_YhB[(size_t)MAXN * 32];
__device__ int     g_hist[MAXN + 1];
__device__ int     g_rowptr[MAXN + 1];
__device__ int     g_cursor[MAXN];
__device__ int     g_edge[MAXE];              // src*32 (half2 row base)
__device__ float   g_dis[MAXN];
__device__ int     g_bcnt[GMAX];
__device__ int     g_tilectr;
__device__ unsigned long long g_tilestate[NTILES];
__device__ unsigned g_ctr = 0;
__device__ unsigned g_gen = 0;

// ---- grid-wide barrier: atomic arrive, volatile-load spin ------------------------------
__device__ __forceinline__ void gridbar(unsigned nb) {
    __syncthreads();
    if (threadIdx.x == 0) {
        __threadfence();
        volatile unsigned* genp = &g_gen;
        unsigned gen = *genp;
        unsigned t = atomicAdd(&g_ctr, 1u);
        if (t == nb - 1u) {
            atomicExch(&g_ctr, 0u);
            __threadfence();
            atomicAdd(&g_gen, 1u);
        } else {
            while (*genp == gen) __nanosleep(64);
        }
        __threadfence();
    }
    __syncthreads();
}

// ---- fused layer: per tile, aggregate 64 nodes into smem, then GEMM the tile ------------
// agg:  xs[r] = dis[v] * (Y[v] + sum_{src in N(v)} Y[src])     (fp32 in smem)
// gemm: out-tile = xs @ W + b [,BN][,ReLU]; write Yout=dis*val fp16, or out fp32 (+pool)
__device__ __forceinline__ void dev_layer(
    const __half2* __restrict__ Yin, __half2* __restrict__ Yout,
    const float* __restrict__ W, const float* __restrict__ bias,
    const float* __restrict__ bg, const float* __restrict__ bbe,
    const float* __restrict__ brm, const float* __restrict__ brv,
    const int* __restrict__ batch,
    float* __restrict__ out, float* __restrict__ hg,
    int n, bool bn, bool relu, bool pool,
    int bid, int nb, float* xs, float* ws)
{
    int t = threadIdx.x;
    int lane = t & 31;
    int w = t >> 5;
    int ntiles = (n + 63) / 64;
    int i4 = t >> 4;
    int j4 = t & 15;

    // load W once per layer (loop-top syncthreads makes it visible before use)
    const float4* W4 = (const float4*)W;
    float4* ws4 = (float4*)ws;
#pragma unroll
    for (int i = 0; i < 4; i++) ws4[t + i * 256] = W4[t + i * 256];

    for (int tb = bid; tb < ntiles; tb += nb) {
        int row0 = tb * 64;
        __syncthreads();   // xs reuse + W visibility (first iter)

        // ---- aggregate: warp w handles rows w*8 .. w*8+7 ----
#pragma unroll 1
        for (int rr = 0; rr < 8; rr++) {
            int r = w * 8 + rr;
            int node = row0 + r;
            float2 res = make_float2(0.f, 0.f);
            if (node < n) {
                int e  = g_rowptr[node];
                int e1 = g_rowptr[node + 1];
                float ds = g_dis[node];
                float2 xv = __half22float2(Yin[(size_t)node * 32 + lane]);
                float2 acc[4];
                acc[0] = xv;                       // self term Y[v]
                acc[1] = make_float2(0.f, 0.f);
                acc[2] = make_float2(0.f, 0.f);
                acc[3] = make_float2(0.f, 0.f);

                for (; e + 8 <= e1; e += 8) {
                    int d[8]; __half2 h[8];
#pragma unroll
                    for (int u = 0; u < 8; u++) d[u] = g_edge[e + u];
#pragma unroll
                    for (int u = 0; u < 8; u++) h[u] = Yin[d[u] + lane];
#pragma unroll
                    for (int u = 0; u < 8; u++) {
                        float2 f = __half22float2(h[u]);
                        acc[u & 3].x += f.x;
                        acc[u & 3].y += f.y;
                    }
                }
                if (e + 4 <= e1) {
                    int d[4]; __half2 h[4];
#pragma unroll
                    for (int u = 0; u < 4; u++) d[u] = g_edge[e + u];
#pragma unroll
                    for (int u = 0; u < 4; u++) h[u] = Yin[d[u] + lane];
#pragma unroll
                    for (int u = 0; u < 4; u++) {
                        float2 f = __half22float2(h[u]);
                        acc[u].x += f.x;
                        acc[u].y += f.y;
                    }
                    e += 4;
                }
                for (; e < e1; e++) {
                    float2 f = __half22float2(Yin[g_edge[e] + lane]);
                    acc[0].x += f.x;
                    acc[0].y += f.y;
                }
                res.x = ds * ((acc[0].x + acc[1].x) + (acc[2].x + acc[3].x));
                res.y = ds * ((acc[0].y + acc[1].y) + (acc[2].y + acc[3].y));
            }
            xs[r * 65 + lane * 2 + 0] = res.x;
            xs[r * 65 + lane * 2 + 1] = res.y;
        }
        __syncthreads();

        // ---- GEMM on the tile ----
        float acc[4][4];
#pragma unroll
        for (int a = 0; a < 4; a++)
#pragma unroll
            for (int c = 0; c < 4; c++) acc[a][c] = 0.f;

#pragma unroll
        for (int k = 0; k < 64; k++) {
            float4 b = *(const float4*)&ws[k * 64 + j4 * 4];
            float a0 = xs[(i4 * 4 + 0) * 65 + k];
            float a1 = xs[(i4 * 4 + 1) * 65 + k];
            float a2 = xs[(i4 * 4 + 2) * 65 + k];
            float a3 = xs[(i4 * 4 + 3) * 65 + k];
            acc[0][0] += a0 * b.x; acc[0][1] += a0 * b.y; acc[0][2] += a0 * b.z; acc[0][3] += a0 * b.w;
            acc[1][0] += a1 * b.x; acc[1][1] += a1 * b.y; acc[1][2] += a1 * b.z; acc[1][3] += a1 * b.w;
            acc[2][0] += a2 * b.x; acc[2][1] += a2 * b.y; acc[2][2] += a2 * b.z; acc[2][3] += a2 * b.w;
            acc[3][0] += a3 * b.x; acc[3][1] += a3 * b.y; acc[3][2] += a3 * b.z; acc[3][3] += a3 * b.w;
        }

        float4 bb = *(const float4*)&bias[j4 * 4];
        float4 sc = make_float4(0.f, 0.f, 0.f, 0.f);
        float4 rm = make_float4(0.f, 0.f, 0.f, 0.f);
        float4 be = make_float4(0.f, 0.f, 0.f, 0.f);
        if (bn) {
            float4 gv = *(const float4*)&bg[j4 * 4];
            float4 rv = *(const float4*)&brv[j4 * 4];
            rm = *(const float4*)&brm[j4 * 4];
            be = *(const float4*)&bbe[j4 * 4];
            sc.x = gv.x * rsqrtf(rv.x + EPS);
            sc.y = gv.y * rsqrtf(rv.y + EPS);
            sc.z = gv.z * rsqrtf(rv.z + EPS);
            sc.w = gv.w * rsqrtf(rv.w + EPS);
        }

        bool singleG = false;
        int gTile = 0;
        if (pool) {
            int lastRow = row0 + 63;
            if (lastRow < n) {
                gTile = batch[row0];
                singleG = (batch[lastRow] == gTile);
            }
        }
        float4 psum = make_float4(0.f, 0.f, 0.f, 0.f);

#pragma unroll
        for (int ii = 0; ii < 4; ii++) {
            int gr = row0 + i4 * 4 + ii;
            if (gr < n) {
                float4 v = make_float4(acc[ii][0] + bb.x, acc[ii][1] + bb.y,
                                       acc[ii][2] + bb.z, acc[ii][3] + bb.w);
                if (bn) {
                    v.x = (v.x - rm.x) * sc.x + be.x;
                    v.y = (v.y - rm.y) * sc.y + be.y;
                    v.z = (v.z - rm.z) * sc.z + be.z;
                    v.w = (v.w - rm.w) * sc.w + be.w;
                }
                if (relu) {
                    v.x = fmaxf(v.x, 0.f); v.y = fmaxf(v.y, 0.f);
                    v.z = fmaxf(v.z, 0.f); v.w = fmaxf(v.w, 0.f);
                }
                if (Yout) {
                    float dg = g_dis[gr];
                    Yout[(size_t)gr * 32 + j4 * 2 + 0] = __floats2half2_rn(dg * v.x, dg * v.y);
                    Yout[(size_t)gr * 32 + j4 * 2 + 1] = __floats2half2_rn(dg * v.z, dg * v.w);
                } else {
                    *(float4*)&out[(size_t)gr * 64 + j4 * 4] = v;
                }
                if (pool) {
                    if (singleG) {
                        psum.x += v.x; psum.y += v.y; psum.z += v.z; psum.w += v.w;
                    } else {
                        int g = batch[gr];
                        float ic = 1.f / fmaxf((float)g_bcnt[g], 1.f);
                        float* h = &hg[g * 64 + j4 * 4];
                        atomicAdd(&h[0], v.x * ic);
                        atomicAdd(&h[1], v.y * ic);
                        atomicAdd(&h[2], v.z * ic);
                        atomicAdd(&h[3], v.w * ic);
                    }
                }
            }
        }

        if (pool && singleG) {
            __syncthreads();                       // all threads done reading xs
            *(float4*)&xs[t * 4] = psum;           // stash partials in xs (W in ws stays live)
            __syncthreads();
            if (t < 64) {
                int jj = t >> 2, comp = t & 3;
                float s = 0.f;
#pragma unroll
                for (int iv = 0; iv < 16; iv++)
                    s += xs[(iv * 16 + jj) * 4 + comp];
                float ic = 1.f / fmaxf((float)g_bcnt[gTile], 1.f);
                atomicAdd(&hg[gTile * 64 + t], s * ic);
            }
        }
    }
    __syncthreads();
}

// ---- the single persistent kernel ---------------------------------------------------------
__global__ void __launch_bounds__(TPB, 4) k_persist(
    const float* __restrict__ x,
    const int* __restrict__ src, const int* __restrict__ dstp,
    const int* __restrict__ batch,
    const float* __restrict__ W1, const float* __restrict__ b1,
    const float* __restrict__ W2, const float* __restrict__ b2,
    const float* __restrict__ W3, const float* __restrict__ b3,
    const float* __restrict__ g1, const float* __restrict__ be1,
    const float* __restrict__ rm1, const float* __restrict__ rv1,
    const float* __restrict__ g2, const float* __restrict__ be2,
    const float* __restrict__ rm2, const float* __restrict__ rv2,
    float* __restrict__ out_h, float* __restrict__ out_hg,
    int n, int e, int gtot)
{
    __shared__ float s_buf[64 * 65 + 64 * 64];
    unsigned nb = gridDim.x;
    int bid = blockIdx.x, tid = threadIdx.x;
    int gtid = bid * TPB + tid;
    int gstride = nb * TPB;
    int* si = (int*)s_buf;
    __shared__ int s_tile, s_prefix;

    // P1: degree histogram + zero pool buffers
    for (int i = gtid; i < e; i += gstride) atomicAdd(&g_hist[dstp[i]], 1);
    for (int i = gtid; i < gtot * D; i += gstride) out_hg[i] = 0.f;
    for (int i = gtid; i < gtot; i += gstride) g_bcnt[i] = 0;
    gridbar(nb);

    // P2: single-pass decoupled-lookback scan; rowptr/cursor/dis, re-zero hist
    int nchunks = (n + TPB - 1) / TPB;
    while (true) {
        if (tid == 0) s_tile = atomicAdd(&g_tilectr, 1);
        __syncthreads();
        int t = s_tile;
        if (t >= nchunks) break;
        int base = t * TPB + tid;
        int v = 0;
        if (base < n) {
            v = g_hist[base];
            g_hist[base] = 0;
            g_dis[base] = rsqrtf((float)v + 1.0f);
        }
        si[tid] = v;
        __syncthreads();
        for (int off = 1; off < 256; off <<= 1) {
            int u = (tid >= off) ? si[tid - off] : 0;
            __syncthreads();
            si[tid] += u;
            __syncthreads();
        }
        int incl = si[tid];
        int bsum = si[255];
        if (tid == 0) {
            unsigned long long pack = t == 0 ? ((2ULL << 32) | (unsigned)bsum)
                                             : ((1ULL << 32) | (unsigned)bsum);
            atomicExch(&g_tilestate[t], pack);
            int pref = 0;
            if (t > 0) {
                int j = t - 1;
                while (true) {
                    unsigned long long st = atomicAdd(&g_tilestate[j], 0ULL);
                    unsigned flag = (unsigned)(st >> 32);
                    if (flag == 2) { pref += (int)(unsigned)st; break; }
                    if (flag == 1) { pref += (int)(unsigned)st; j--; continue; }
                    __nanosleep(40);
                }
                atomicExch(&g_tilestate[t], (2ULL << 32) | (unsigned)(pref + bsum));
            }
            s_prefix = pref;
        }
        __syncthreads();
        int ex = s_prefix + incl - v;
        if (base < n) { g_rowptr[base] = ex; g_cursor[base] = ex; }
        if (base == n - 1) g_rowptr[n] = ex + v;
        __syncthreads();
    }
    gridbar(nb);

    // P3: CSR fill (src only) + stage Y = dis*x fp16 + batch counts + reset scan state
    for (int i = gtid; i < e; i += gstride) {
        int s = src[i], d = dstp[i];
        int pos = atomicAdd(&g_cursor[d], 1);
        g_edge[pos] = s << 5;                       // half2-row base = src*32
    }
    {
        const float2* X2 = (const float2*)x;
        for (int i = gtid; i < n * 32; i += gstride) {
            float dv = g_dis[i >> 5];
            float2 f = X2[i];
            g_YhA[i] = __floats2half2_rn(dv * f.x, dv * f.y);
        }
    }
    for (int i = gtid; i < n; i += gstride) atomicAdd(&g_bcnt[batch[i]], 1);
    if (gtid < NTILES) g_tilestate[gtid] = 0ULL;
    if (gtid == 0) g_tilectr = 0;
    gridbar(nb);

    float* xs = s_buf;
    float* ws = s_buf + 64 * 65;

    // layer 1: YhA -> YhB
    dev_layer(g_YhA, g_YhB, W1, b1, g1, be1, rm1, rv1, nullptr, nullptr, nullptr,
              n, true, true, false, bid, nb, xs, ws);
    gridbar(nb);
    // layer 2: YhB -> YhA
    dev_layer(g_YhB, g_YhA, W2, b2, g2, be2, rm2, rv2, nullptr, nullptr, nullptr,
              n, true, true, false, bid, nb, xs, ws);
    gridbar(nb);
    // layer 3: YhA -> fp32 out + fused pool
    dev_layer(g_YhA, nullptr, W3, b3, nullptr, nullptr, nullptr, nullptr, batch,
              out_h, out_hg, n, false, false, true, bid, nb, xs, ws);
}

// ---- launch ---------------------------------------------------------------------------------
extern "C" void kernel_launch(void* const* d_in, const int* in_sizes, int n_in,
                              void* d_out, int out_size)
{
    const float* x    = (const float*)d_in[0];
    const int*   ei   = (const int*)d_in[1];
    const int*   batch= (const int*)d_in[2];

    const float *W1, *W2, *W3, *b1, *b2, *b3;
    if (in_sizes[4] == D * D) {
        W1 = (const float*)d_in[3]; W2 = (const float*)d_in[4]; W3 = (const float*)d_in[5];
        b1 = (const float*)d_in[6]; b2 = (const float*)d_in[7]; b3 = (const float*)d_in[8];
    } else {
        W1 = (const float*)d_in[3]; b1 = (const float*)d_in[4];
        W2 = (const float*)d_in[5]; b2 = (const float*)d_in[6];
        W3 = (const float*)d_in[7]; b3 = (const float*)d_in[8];
    }
    const float* g1   = (const float*)d_in[9];
    const float* be1  = (const float*)d_in[10];
    const float* rm1  = (const float*)d_in[11];
    const float* rv1  = (const float*)d_in[12];
    const float* g2   = (const float*)d_in[13];
    const float* be2  = (const float*)d_in[14];
    const float* rm2  = (const float*)d_in[15];
    const float* rv2  = (const float*)d_in[16];

    int n = in_sizes[0] / D;
    int e = in_sizes[1] / 2;
    int gtot = (out_size - n * D) / D;

    const int* src = ei;
    const int* dst = ei + e;

    float* out_h  = (float*)d_out;
    float* out_hg = (float*)d_out + (size_t)n * D;

    int dev = 0, nsm = 148;
    cudaGetDevice(&dev);
    cudaDeviceGetAttribute(&nsm, cudaDevAttrMultiProcessorCount, dev);
    int maxb = 1;
    cudaOccupancyMaxActiveBlocksPerMultiprocessor(&maxb, k_persist, TPB, 0);
    if (maxb < 1) maxb = 1;
    int grid = nsm * maxb;

    k_persist<<<grid, TPB>>>(x, src, dst, batch,
                             W1, b1, W2, b2, W3, b3,
                             g1, be1, rm1, rv1, g2, be2, rm2, rv2,
                             out_h, out_hg, n, e, gtot);
}